// round 9
// baseline (speedup 1.0000x reference)
#include <cuda_runtime.h>
#include <cuda_bf16.h>

#define UMAX 4096
#define NT   256

__device__ __forceinline__ float blockReduceSum(float v, float* sred) {
    int lane = threadIdx.x & 31, wid = threadIdx.x >> 5;
    #pragma unroll
    for (int o = 16; o; o >>= 1) v += __shfl_down_sync(0xffffffffu, v, o);
    if (lane == 0) sred[wid] = v;
    __syncthreads();
    if (threadIdx.x < 32) {
        float x = (lane < (NT / 32)) ? sred[lane] : 0.f;
        #pragma unroll
        for (int o = 4; o; o >>= 1) x += __shfl_down_sync(0xffffffffu, x, o);
        if (lane == 0) sred[0] = x;
    }
    __syncthreads();
    float r = sred[0];
    __syncthreads();
    return r;
}

__global__ void __launch_bounds__(NT, 4) proj_kernel(
    const float* __restrict__ W,    // pause_weight_unit   [B,U]
    const float* __restrict__ BS,   // boundary_score_unit [B,U]
    const float* __restrict__ MK,   // unit_mask           [B,U] (prefix of ones)
    const float* __restrict__ BUD,  // pause_budget_win    [B]
    const float* __restrict__ PV,   // previous_pause_exec [B,U]
    const void*  __restrict__ FR,   // commit_frontier     [B] int32 or int64
    float* __restrict__ O,          // out [B,U]
    int U, int Bn)
{
    __shared__ float    s_scores[UMAX];   // 16KB
    __shared__ unsigned s_hist[256];
    __shared__ unsigned s_wtot[NT / 32];
    __shared__ float    s_red[NT / 32];
    __shared__ int      s_T, s_Lv, s_is64;
    __shared__ unsigned s_digit, s_krn;

    const int row  = blockIdx.x;
    const int tid  = threadIdx.x;
    const int lane = tid & 31;
    const int wid  = tid >> 5;

    const float* w   = W  + (size_t)row * U;
    const float* bsc = BS + (size_t)row * U;
    const float* mk  = MK + (size_t)row * U;
    const float* pv  = PV + (size_t)row * U;
    float*       out = O  + (size_t)row * U;

    if (tid == 0) { s_T = 0; s_Lv = 0; }
    s_hist[tid] = 0;
    // frontier dtype detection (warp 2): int64 little-endian => odd 32-bit
    // words all zero (values are small nonneg); int32 uniform[0,2048) never is.
    if (wid == 2) {
        const int* fi = (const int*)FR;
        int idx = 2 * lane + 1;
        int vv  = (idx < Bn) ? fi[idx] : 0;
        unsigned bal = __ballot_sync(0xffffffffu, vv == 0);
        if (lane == 0) s_is64 = (bal == 0xffffffffu) ? 1 : 0;
    }
    __syncthreads();

    // ---- two-level search for L (mask is a contiguous prefix of ones) ----
    if (tid < 64) {
        int pos = tid * 64;
        if (pos < U && mk[pos] > 0.5f) atomicMax(&s_T, tid);
    }
    __syncthreads();
    {
        int T = s_T;
        if (tid < 64) {
            int pos = T * 64 + tid;
            if (pos < U && mk[pos] > 0.5f) atomicMax(&s_Lv, pos + 1);
        }
    }
    __syncthreads();
    const int   L  = s_Lv;
    const float Lf = (float)L;
    const int   L4 = L & ~3;

    // keep_k: jnp.round == round-half-even == rintf (RN mode)
    float kf = fmaxf(1.0f, rintf(Lf * 0.35f));
    kf = fminf(kf, fmaxf(Lf, 1.0f));
    const bool no_gate = (kf >= Lf);

    auto histAdd = [&](unsigned u, int shift) {
        unsigned d = (u >> shift) & 0xFFu;
        unsigned m = __match_any_sync(__activemask(), d);
        if ((int)(__ffs(m) - 1) == lane)
            atomicAdd(&s_hist[d], (unsigned)__popc(m));
    };

    // ---- phase A: scores into smem + fused pass-1 (top byte) histogram ----
    for (int j = tid * 4; j < L4; j += NT * 4) {
        float4 a = *(const float4*)(w + j);
        float4 b = *(const float4*)(bsc + j);
        float4 s;
        s.x = fmaxf(a.x, 0.f) + 0.15f * (0.1f + fmaxf(b.x, 0.f));
        s.y = fmaxf(a.y, 0.f) + 0.15f * (0.1f + fmaxf(b.y, 0.f));
        s.z = fmaxf(a.z, 0.f) + 0.15f * (0.1f + fmaxf(b.z, 0.f));
        s.w = fmaxf(a.w, 0.f) + 0.15f * (0.1f + fmaxf(b.w, 0.f));
        *(float4*)(s_scores + j) = s;   // strictly positive -> bits preserve order
        histAdd(__float_as_uint(s.x), 24);
        histAdd(__float_as_uint(s.y), 24);
        histAdd(__float_as_uint(s.z), 24);
        histAdd(__float_as_uint(s.w), 24);
    }
    for (int j = L4 + tid; j < L; j += NT) {
        float s = fmaxf(w[j], 0.f) + 0.15f * (0.1f + fmaxf(bsc[j], 0.f));
        s_scores[j] = s;
        histAdd(__float_as_uint(s), 24);
    }
    __syncthreads();

    // ---- exact radix select: k-th largest among s_scores[0..L) ----
    unsigned prefix = 0;
    unsigned kr = (unsigned)(int)kf;
    for (int shift = 24; shift >= 0; shift -= 8) {
        if (shift != 24) {
            s_hist[tid] = 0;
            __syncthreads();
            const unsigned pmask = 0xFFFFFFFFu << (shift + 8);
            for (int j = tid * 4; j < L4; j += NT * 4) {
                uint4 v = *(const uint4*)(s_scores + j);
                if ((v.x & pmask) == prefix) histAdd(v.x, shift);
                if ((v.y & pmask) == prefix) histAdd(v.y, shift);
                if ((v.z & pmask) == prefix) histAdd(v.z, shift);
                if ((v.w & pmask) == prefix) histAdd(v.w, shift);
            }
            for (int j = L4 + tid; j < L; j += NT) {
                unsigned v = __float_as_uint(s_scores[j]);
                if ((v & pmask) == prefix) histAdd(v, shift);
            }
        }
        __syncthreads();
        unsigned c = s_hist[tid];
        unsigned s = c;
        #pragma unroll
        for (int o = 1; o < 32; o <<= 1) {
            unsigned t = __shfl_down_sync(0xffffffffu, s, o);
            if (lane + o < 32) s += t;
        }
        if (lane == 0) s_wtot[wid] = s;
        __syncthreads();
        unsigned above = 0;
        #pragma unroll
        for (int ww = 0; ww < NT / 32; ww++) if (ww > wid) above += s_wtot[ww];
        unsigned suf = s + above;          // count with digit >= tid under prefix
        if (suf >= kr && (suf - c) < kr) { // unique crossing bin
            s_digit = (unsigned)tid;
            s_krn   = kr - (suf - c);
        }
        __syncthreads();
        prefix |= (s_digit << shift);
        kr = s_krn;
        __syncthreads();
    }
    const float thr = __uint_as_float(prefix);

    // ---- frontier ----
    long long fr;
    if (s_is64) fr = ((const long long*)FR)[row];
    else        fr = (long long)((const int*)FR)[row];
    int vf  = (int)(fr < 0 ? 0 : (fr > (long long)U ? (long long)U : fr));
    int vfc = min(vf, L);

    const float invT = 1.0f / 0.12f;
    float psum = 0.f, csum = 0.f;

    // prefix region [0, vfc): psum + write out = prev  (streaming stores: out
    // is never re-read by the kernel -> evict-first keeps L2 for the inputs)
    {
        int v4 = vfc & ~3;
        for (int j = tid * 4; j < v4; j += NT * 4) {
            float4 p = *(const float4*)(pv + j);
            psum += (p.x + p.y) + (p.z + p.w);
            __stcs((float4*)(out + j), p);
        }
        for (int j = v4 + tid; j < vfc; j += NT) {
            float v = pv[j];
            psum += v;
            __stcs(out + j, v);
        }
    }
    // tail region [vfc, L): gate, csum, stash selected back into smem
    const int th  = min(L, (vfc + 3) & ~3);
    const int tl4 = th + ((L - th) & ~3);
    {
        for (int j = vfc + tid; j < th; j += NT) {
            float s = s_scores[j];
            float sel = no_gate ? s : __fdividef(s, 1.f + __expf((thr - s) * invT));
            csum += sel;
            s_scores[j] = sel;
        }
        for (int j = th + tid * 4; j < tl4; j += NT * 4) {
            float4 s4 = *(const float4*)(s_scores + j);
            float4 r;
            if (no_gate) r = s4;
            else {
                r.x = __fdividef(s4.x, 1.f + __expf((thr - s4.x) * invT));
                r.y = __fdividef(s4.y, 1.f + __expf((thr - s4.y) * invT));
                r.z = __fdividef(s4.z, 1.f + __expf((thr - s4.z) * invT));
                r.w = __fdividef(s4.w, 1.f + __expf((thr - s4.w) * invT));
            }
            csum += (r.x + r.y) + (r.z + r.w);
            *(float4*)(s_scores + j) = r;
        }
        for (int j = tl4 + tid; j < L; j += NT) {
            float s = s_scores[j];
            float sel = no_gate ? s : __fdividef(s, 1.f + __expf((thr - s) * invT));
            csum += sel;
            s_scores[j] = sel;
        }
    }
    float psum_t = blockReduceSum(psum, s_red);
    float csum_t = blockReduceSum(csum, s_red);

    float scale = 0.f, fb = 0.f;
    int tc = L - vfc;
    if (tc > 0) {
        float ts = (float)tc;                 // tail_sum
        fb = 1e-6f / ts;                      // fallback * EPS per element
        float remaining = fmaxf(BUD[row] - psum_t, 0.f);
        float total = fmaxf(csum_t + ts * fb, 1e-6f);
        scale = remaining / total;
    }

    // ---- write tail + trailing zeros ----
    for (int j = vfc + tid; j < th; j += NT)
        __stcs(out + j, (s_scores[j] + fb) * scale);
    for (int j = th + tid * 4; j < tl4; j += NT * 4) {
        float4 s4 = *(const float4*)(s_scores + j);
        float4 r = make_float4((s4.x + fb) * scale, (s4.y + fb) * scale,
                               (s4.z + fb) * scale, (s4.w + fb) * scale);
        __stcs((float4*)(out + j), r);
    }
    for (int j = tl4 + tid; j < L; j += NT)
        __stcs(out + j, (s_scores[j] + fb) * scale);

    const int zh  = min(U, (L + 3) & ~3);
    const int zl4 = zh + ((U - zh) & ~3);
    for (int j = L + tid; j < zh; j += NT) __stcs(out + j, 0.f);
    for (int j = zh + tid * 4; j < zl4; j += NT * 4)
        __stcs((float4*)(out + j), make_float4(0.f, 0.f, 0.f, 0.f));
    for (int j = zl4 + tid; j < U; j += NT) __stcs(out + j, 0.f);
}

extern "C" void kernel_launch(void* const* d_in, const int* in_sizes, int n_in,
                              void* d_out, int out_size) {
    const float* w    = (const float*)d_in[0];
    const float* bsc  = (const float*)d_in[1];
    const float* mk   = (const float*)d_in[2];
    const float* bud  = (const float*)d_in[3];
    const float* prev = (const float*)d_in[4];
    const void*  fr   = (const void*)d_in[5];
    int B = in_sizes[3];            // pause_budget_win is [B]
    int U = in_sizes[0] / B;        // row length
    proj_kernel<<<B, NT>>>(w, bsc, mk, bud, prev, fr, (float*)d_out, U, B);
}

// round 12
// speedup vs baseline: 1.1858x; 1.1858x over previous
#include <cuda_runtime.h>
#include <cuda_bf16.h>

#define UMAX  4096
#define NT    256
#define NBINS 4096          // 12-bit digit histogram, reused for both passes
#define BPT   (NBINS / NT)  // 16 bins per thread
#define USCALE 8388608.0f   // 2^23 : u = floor(s * 2^23), 24-bit monotone key

__device__ __forceinline__ float blockReduceSum(float v, float* sred) {
    int lane = threadIdx.x & 31, wid = threadIdx.x >> 5;
    #pragma unroll
    for (int o = 16; o; o >>= 1) v += __shfl_down_sync(0xffffffffu, v, o);
    if (lane == 0) sred[wid] = v;
    __syncthreads();
    if (threadIdx.x < 32) {
        float x = (lane < (NT / 32)) ? sred[lane] : 0.f;
        #pragma unroll
        for (int o = 4; o; o >>= 1) x += __shfl_down_sync(0xffffffffu, x, o);
        if (lane == 0) sred[0] = x;
    }
    __syncthreads();
    float r = sred[0];
    __syncthreads();
    return r;
}

__global__ void __launch_bounds__(NT, 4) proj_kernel(
    const float* __restrict__ W,    // pause_weight_unit   [B,U]
    const float* __restrict__ BS,   // boundary_score_unit [B,U]
    const float* __restrict__ MK,   // unit_mask           [B,U] (prefix of ones)
    const float* __restrict__ BUD,  // pause_budget_win    [B]
    const float* __restrict__ PV,   // previous_pause_exec [B,U]
    const void*  __restrict__ FR,   // commit_frontier     [B] int32 or int64
    float* __restrict__ O,          // out [B,U]
    int U, int Bn)
{
    __shared__ float    s_scores[UMAX];   // 16KB
    __shared__ unsigned s_hist[NBINS];    // 16KB
    __shared__ unsigned s_wtot[NT / 32];
    __shared__ float    s_red[NT / 32];
    __shared__ int      s_T, s_Lv, s_is64;
    __shared__ unsigned s_digit, s_krn;

    const int row  = blockIdx.x;
    const int tid  = threadIdx.x;
    const int lane = tid & 31;
    const int wid  = tid >> 5;

    const float* w   = W  + (size_t)row * U;
    const float* bsc = BS + (size_t)row * U;
    const float* mk  = MK + (size_t)row * U;
    const float* pv  = PV + (size_t)row * U;
    float*       out = O  + (size_t)row * U;

    // ---- init: zero histogram, misc, frontier dtype detect ----
    {
        uint4 z = make_uint4(0, 0, 0, 0);
        #pragma unroll
        for (int i = 0; i < BPT / 4; i++)
            *(uint4*)(s_hist + tid * BPT + i * 4) = z;
    }
    if (tid == 0) { s_T = 0; s_Lv = 0; }
    if (wid == 2) {
        // int64 little-endian => odd 32-bit words all zero (values small nonneg);
        // int32 uniform[0,2048) essentially never is.
        const int* fi = (const int*)FR;
        int idx = 2 * lane + 1;
        int vv  = (idx < Bn) ? fi[idx] : 0;
        unsigned bal = __ballot_sync(0xffffffffu, vv == 0);
        if (lane == 0) s_is64 = (bal == 0xffffffffu) ? 1 : 0;
    }
    __syncthreads();

    // ---- two-level search for L (mask is a contiguous prefix of ones) ----
    if (tid < 64) {
        int pos = tid * 64;
        if (pos < U && mk[pos] > 0.5f) atomicMax(&s_T, tid);
    }
    __syncthreads();
    {
        int T = s_T;
        if (tid < 64) {
            int pos = T * 64 + tid;
            if (pos < U && mk[pos] > 0.5f) atomicMax(&s_Lv, pos + 1);
        }
    }
    __syncthreads();
    const int   L  = s_Lv;
    const float Lf = (float)L;
    const int   L4 = L & ~3;

    // keep_k: jnp.round == round-half-even == rintf (RN mode)
    float kf = fmaxf(1.0f, rintf(Lf * 0.35f));
    kf = fminf(kf, fmaxf(Lf, 1.0f));
    const bool no_gate = (kf >= Lf);

    // ---- phase A: scores -> smem, 24-bit key top-12 histogram ----
    for (int j = tid * 4; j < L4; j += NT * 4) {
        float4 a = *(const float4*)(w + j);
        float4 b = *(const float4*)(bsc + j);
        float4 s;
        s.x = fmaxf(a.x, 0.f) + 0.15f * (0.1f + fmaxf(b.x, 0.f));
        s.y = fmaxf(a.y, 0.f) + 0.15f * (0.1f + fmaxf(b.y, 0.f));
        s.z = fmaxf(a.z, 0.f) + 0.15f * (0.1f + fmaxf(b.z, 0.f));
        s.w = fmaxf(a.w, 0.f) + 0.15f * (0.1f + fmaxf(b.w, 0.f));
        *(float4*)(s_scores + j) = s;
        atomicAdd(&s_hist[((unsigned)(s.x * USCALE)) >> 12], 1u);
        atomicAdd(&s_hist[((unsigned)(s.y * USCALE)) >> 12], 1u);
        atomicAdd(&s_hist[((unsigned)(s.z * USCALE)) >> 12], 1u);
        atomicAdd(&s_hist[((unsigned)(s.w * USCALE)) >> 12], 1u);
    }
    for (int j = L4 + tid; j < L; j += NT) {
        float s = fmaxf(w[j], 0.f) + 0.15f * (0.1f + fmaxf(bsc[j], 0.f));
        s_scores[j] = s;
        atomicAdd(&s_hist[((unsigned)(s * USCALE)) >> 12], 1u);
    }
    __syncthreads();

    // ---- pass 1: find crossing top-digit bin for rank kr (k-th largest) ----
    unsigned kr = (unsigned)(int)kf;
    unsigned bsel;
    {
        // thread t owns bins [t*16, (t+1)*16)
        unsigned total = 0;
        #pragma unroll
        for (int i = 0; i < BPT / 4; i++) {
            uint4 v = *(const uint4*)(s_hist + tid * BPT + i * 4);
            total += v.x + v.y + v.z + v.w;
        }
        // block suffix-exclusive over thread totals (higher tid = higher bins)
        unsigned sfx = total;
        #pragma unroll
        for (int o = 1; o < 32; o <<= 1) {
            unsigned t2 = __shfl_down_sync(0xffffffffu, sfx, o);
            if (lane + o < 32) sfx += t2;
        }
        if (lane == 0) s_wtot[wid] = sfx;
        __syncthreads();
        unsigned aboveW = 0;
        #pragma unroll
        for (int ww = 0; ww < NT / 32; ww++) if (ww > wid) aboveW += s_wtot[ww];
        unsigned above = (sfx - total) + aboveW;  // elements in bins above my segment
        if (above < kr && above + total >= kr) {  // unique owner of crossing bin
            unsigned run = above;
            #pragma unroll 1
            for (int i = BPT - 1; i >= 0; --i) {
                unsigned cb = s_hist[tid * BPT + i];
                run += cb;
                if (run >= kr) {
                    s_digit = (unsigned)(tid * BPT + i);
                    s_krn   = kr - (run - cb);
                    break;
                }
            }
        }
        __syncthreads();
        bsel = s_digit;
        kr   = s_krn;
        // re-zero own bins for pass 2 (all reads of s_hist done)
        uint4 z = make_uint4(0, 0, 0, 0);
        #pragma unroll
        for (int i = 0; i < BPT / 4; i++)
            *(uint4*)(s_hist + tid * BPT + i * 4) = z;
    }
    __syncthreads();

    // ---- pass 2: histogram low 12 bits of keys in the crossing bin ----
    for (int j = tid * 4; j < L4; j += NT * 4) {
        float4 s4 = *(const float4*)(s_scores + j);
        unsigned ux = (unsigned)(s4.x * USCALE);
        unsigned uy = (unsigned)(s4.y * USCALE);
        unsigned uz = (unsigned)(s4.z * USCALE);
        unsigned uw = (unsigned)(s4.w * USCALE);
        if ((ux >> 12) == bsel) atomicAdd(&s_hist[ux & 0xFFFu], 1u);
        if ((uy >> 12) == bsel) atomicAdd(&s_hist[uy & 0xFFFu], 1u);
        if ((uz >> 12) == bsel) atomicAdd(&s_hist[uz & 0xFFFu], 1u);
        if ((uw >> 12) == bsel) atomicAdd(&s_hist[uw & 0xFFFu], 1u);
    }
    for (int j = L4 + tid; j < L; j += NT) {
        unsigned u = (unsigned)(s_scores[j] * USCALE);
        if ((u >> 12) == bsel) atomicAdd(&s_hist[u & 0xFFFu], 1u);
    }
    __syncthreads();

    // ---- pass 2 selection: low-12 crossing digit ----
    {
        unsigned total = 0;
        #pragma unroll
        for (int i = 0; i < BPT / 4; i++) {
            uint4 v = *(const uint4*)(s_hist + tid * BPT + i * 4);
            total += v.x + v.y + v.z + v.w;
        }
        unsigned sfx = total;
        #pragma unroll
        for (int o = 1; o < 32; o <<= 1) {
            unsigned t2 = __shfl_down_sync(0xffffffffu, sfx, o);
            if (lane + o < 32) sfx += t2;
        }
        if (lane == 0) s_wtot[wid] = sfx;
        __syncthreads();
        unsigned aboveW = 0;
        #pragma unroll
        for (int ww = 0; ww < NT / 32; ww++) if (ww > wid) aboveW += s_wtot[ww];
        unsigned above = (sfx - total) + aboveW;
        if (above < kr && above + total >= kr) {
            unsigned run = above;
            #pragma unroll 1
            for (int i = BPT - 1; i >= 0; --i) {
                unsigned cb = s_hist[tid * BPT + i];
                run += cb;
                if (run >= kr) {
                    s_digit = (unsigned)(tid * BPT + i);
                    break;
                }
            }
        }
        __syncthreads();
    }
    const unsigned thr_u = (bsel << 12) | s_digit;
    const float thr = (float)thr_u * (1.0f / USCALE);   // within 2^-23 of exact k-th score

    // ---- frontier ----
    long long fr;
    if (s_is64) fr = ((const long long*)FR)[row];
    else        fr = (long long)((const int*)FR)[row];
    int vf  = (int)(fr < 0 ? 0 : (fr > (long long)U ? (long long)U : fr));
    int vfc = min(vf, L);

    const float invT = 1.0f / 0.12f;
    float psum = 0.f, csum = 0.f;

    // prefix region [0, vfc): psum + out = prev (streaming stores)
    {
        int v4 = vfc & ~3;
        for (int j = tid * 4; j < v4; j += NT * 4) {
            float4 p = *(const float4*)(pv + j);
            psum += (p.x + p.y) + (p.z + p.w);
            __stcs((float4*)(out + j), p);
        }
        for (int j = v4 + tid; j < vfc; j += NT) {
            float v = pv[j];
            psum += v;
            __stcs(out + j, v);
        }
    }
    // tail region [vfc, L): gate, csum, stash selected back into smem
    const int th  = min(L, (vfc + 3) & ~3);
    const int tl4 = th + ((L - th) & ~3);
    {
        for (int j = vfc + tid; j < th; j += NT) {
            float s = s_scores[j];
            float sel = no_gate ? s : __fdividef(s, 1.f + __expf((thr - s) * invT));
            csum += sel;
            s_scores[j] = sel;
        }
        for (int j = th + tid * 4; j < tl4; j += NT * 4) {
            float4 s4 = *(const float4*)(s_scores + j);
            float4 r;
            if (no_gate) r = s4;
            else {
                r.x = __fdividef(s4.x, 1.f + __expf((thr - s4.x) * invT));
                r.y = __fdividef(s4.y, 1.f + __expf((thr - s4.y) * invT));
                r.z = __fdividef(s4.z, 1.f + __expf((thr - s4.z) * invT));
                r.w = __fdividef(s4.w, 1.f + __expf((thr - s4.w) * invT));
            }
            csum += (r.x + r.y) + (r.z + r.w);
            *(float4*)(s_scores + j) = r;
        }
        for (int j = tl4 + tid; j < L; j += NT) {
            float s = s_scores[j];
            float sel = no_gate ? s : __fdividef(s, 1.f + __expf((thr - s) * invT));
            csum += sel;
            s_scores[j] = sel;
        }
    }
    float psum_t = blockReduceSum(psum, s_red);
    float csum_t = blockReduceSum(csum, s_red);

    float scale = 0.f, fb = 0.f;
    int tc = L - vfc;
    if (tc > 0) {
        float ts = (float)tc;                 // tail_sum
        fb = 1e-6f / ts;                      // fallback * EPS per element
        float remaining = fmaxf(BUD[row] - psum_t, 0.f);
        float total = fmaxf(csum_t + ts * fb, 1e-6f);
        scale = remaining / total;
    }

    // ---- write tail + trailing zeros ----
    for (int j = vfc + tid; j < th; j += NT)
        __stcs(out + j, (s_scores[j] + fb) * scale);
    for (int j = th + tid * 4; j < tl4; j += NT * 4) {
        float4 s4 = *(const float4*)(s_scores + j);
        float4 r = make_float4((s4.x + fb) * scale, (s4.y + fb) * scale,
                               (s4.z + fb) * scale, (s4.w + fb) * scale);
        __stcs((float4*)(out + j), r);
    }
    for (int j = tl4 + tid; j < L; j += NT)
        __stcs(out + j, (s_scores[j] + fb) * scale);

    const int zh  = min(U, (L + 3) & ~3);
    const int zl4 = zh + ((U - zh) & ~3);
    for (int j = L + tid; j < zh; j += NT) __stcs(out + j, 0.f);
    for (int j = zh + tid * 4; j < zl4; j += NT * 4)
        __stcs((float4*)(out + j), make_float4(0.f, 0.f, 0.f, 0.f));
    for (int j = zl4 + tid; j < U; j += NT) __stcs(out + j, 0.f);
}

extern "C" void kernel_launch(void* const* d_in, const int* in_sizes, int n_in,
                              void* d_out, int out_size) {
    const float* w    = (const float*)d_in[0];
    const float* bsc  = (const float*)d_in[1];
    const float* mk   = (const float*)d_in[2];
    const float* bud  = (const float*)d_in[3];
    const float* prev = (const float*)d_in[4];
    const void*  fr   = (const void*)d_in[5];
    int B = in_sizes[3];            // pause_budget_win is [B]
    int U = in_sizes[0] / B;        // row length
    proj_kernel<<<B, NT>>>(w, bsc, mk, bud, prev, fr, (float*)d_out, U, B);
}